// round 3
// baseline (speedup 1.0000x reference)
#include <cuda_runtime.h>
#include <cuda_bf16.h>
#include <math.h>

// ---------------- problem constants ----------------
#define NN    20000     // nodes
#define EE    5000      // hyperedges
#define NNZV  200000    // incidences
#define DH    6         // sheaf dim d
#define HID   9         // MLP hidden
#define FIN   256       // input features
#define OUTD  4968      // output dim
#define PROJ  54        // DH*HID
#define ROW12 12        // padded row stride (floats) for 9-wide rows
#define NLAY  2

// ---------------- scratch (static device globals; no runtime alloc) ----------------
__device__ __align__(16) float g_xproj[NN * PROJ];      // doubles as x_state (N*d, 9) packed
__device__ __align__(16) float g_xm[NN * ROW12];        // node means, stride 12
__device__ __align__(16) float g_em[EE * ROW12];        // edge means, stride 12
__device__ __align__(16) float g_hsheaf[(size_t)NNZV * DH];
__device__ int   g_cnt_node[NN];
__device__ int   g_cnt_edge[EE];
__device__ __align__(16) float g_h0[(size_t)NN * DH * ROW12];   // (N*d, 12)
__device__ __align__(16) float g_m[(size_t)EE * DH * ROW12];    // (E*d, 12)
__device__ __align__(16) float g_acc[(size_t)NN * DH * ROW12];  // (N*d, 12)

// ---------------- zero kernels ----------------
__global__ void zero_counts_kernel() {
    int i = blockIdx.x * blockDim.x + threadIdx.x;
    if (i < NN) g_cnt_node[i] = 0;
    if (i < EE) g_cnt_edge[i] = 0;
}

__global__ void zero_layer_kernel() {
    int i = blockIdx.x * blockDim.x + threadIdx.x;
    if (i < NN * DH * ROW12) g_acc[i] = 0.f;
    if (i < EE * DH * ROW12) g_m[i] = 0.f;
}

// ---------------- input projection + per-row mean over d ----------------
// 8 rows per block, 64 threads. rows [0,NN) -> x, rows [NN,NN+EE) -> hyperedge_attr
__global__ void proj_kernel(const float* __restrict__ x,
                            const float* __restrict__ ha,
                            const float* __restrict__ W,   // (256,54) row-major
                            const float* __restrict__ b)   // (54,)
{
    __shared__ float sx[8][FIN];
    __shared__ float sout[8][PROJ];
    int r0 = blockIdx.x * 8;
    int t  = threadIdx.x;

    #pragma unroll
    for (int rr = 0; rr < 8; rr++) {
        int r = r0 + rr;
        if (r >= NN + EE) break;
        const float* src = (r < NN) ? (x + (size_t)r * FIN)
                                    : (ha + (size_t)(r - NN) * FIN);
        for (int c = t; c < FIN; c += 64) sx[rr][c] = src[c];
    }
    __syncthreads();

    if (t < PROJ) {
        float acc[8];
        float bt = b[t];
        #pragma unroll
        for (int rr = 0; rr < 8; rr++) acc[rr] = bt;
        #pragma unroll 4
        for (int c = 0; c < FIN; c++) {
            float w = W[c * PROJ + t];
            #pragma unroll
            for (int rr = 0; rr < 8; rr++) acc[rr] += w * sx[rr][c];
        }
        #pragma unroll
        for (int rr = 0; rr < 8; rr++) {
            int r = r0 + rr;
            if (r >= NN + EE) break;
            if (r < NN) g_xproj[(size_t)r * PROJ + t] = acc[rr];
            sout[rr][t] = acc[rr];
        }
    }
    __syncthreads();

    if (t < HID) {
        #pragma unroll
        for (int rr = 0; rr < 8; rr++) {
            int r = r0 + rr;
            if (r >= NN + EE) break;
            float s = 0.f;
            #pragma unroll
            for (int j = 0; j < DH; j++) s += sout[rr][j * HID + t];
            s *= (1.0f / DH);
            if (r < NN) g_xm[(size_t)r * ROW12 + t] = s;
            else        g_em[(size_t)(r - NN) * ROW12 + t] = s;
        }
    }
}

// ---------------- sheaf builder: LN(18) -> Linear(18->6) -> sigmoid; also degree counts ---------
__global__ void sheaf_kernel(const int* __restrict__ ni, const int* __restrict__ ei,
                             const float* __restrict__ lng, const float* __restrict__ lnb,
                             const float* __restrict__ sw,  const float* __restrict__ sb)
{
    __shared__ float s_sw[2 * HID * DH];  // 108
    __shared__ float s_sb[DH];
    __shared__ float s_g[2 * HID], s_b[2 * HID];
    int t = threadIdx.x;
    if (t < 2 * HID * DH) s_sw[t] = sw[t];
    if (t < DH) s_sb[t] = sb[t];
    if (t < 2 * HID) { s_g[t] = lng[t]; s_b[t] = lnb[t]; }
    __syncthreads();

    int k = blockIdx.x * blockDim.x + threadIdx.x;
    if (k >= NNZV) return;
    int n = ni[k], e = ei[k];

    float v[2 * HID];
    {
        const float4 a0 = *(const float4*)(g_xm + (size_t)n * ROW12);
        const float4 a1 = *(const float4*)(g_xm + (size_t)n * ROW12 + 4);
        v[0]=a0.x; v[1]=a0.y; v[2]=a0.z; v[3]=a0.w;
        v[4]=a1.x; v[5]=a1.y; v[6]=a1.z; v[7]=a1.w;
        v[8] = g_xm[(size_t)n * ROW12 + 8];
        const float4 b0 = *(const float4*)(g_em + (size_t)e * ROW12);
        const float4 b1 = *(const float4*)(g_em + (size_t)e * ROW12 + 4);
        v[9]=b0.x; v[10]=b0.y; v[11]=b0.z; v[12]=b0.w;
        v[13]=b1.x; v[14]=b1.y; v[15]=b1.z; v[16]=b1.w;
        v[17] = g_em[(size_t)e * ROW12 + 8];
    }
    float mean = 0.f;
    #pragma unroll
    for (int i = 0; i < 18; i++) mean += v[i];
    mean *= (1.0f / 18.0f);
    float var = 0.f;
    #pragma unroll
    for (int i = 0; i < 18; i++) { float d = v[i] - mean; var += d * d; }
    var *= (1.0f / 18.0f);
    float rs = rsqrtf(var + 1e-5f);
    float y[18];
    #pragma unroll
    for (int i = 0; i < 18; i++) y[i] = (v[i] - mean) * rs * s_g[i] + s_b[i];

    #pragma unroll
    for (int j = 0; j < DH; j++) {
        float z = s_sb[j];
        #pragma unroll
        for (int i = 0; i < 18; i++) z += y[i] * s_sw[i * DH + j];
        float h = 1.0f / (1.0f + expf(-z));
        g_hsheaf[(size_t)k * DH + j] = h;
    }
    atomicAdd(&g_cnt_node[n], 1);
    atomicAdd(&g_cnt_edge[e], 1);
}

// ---------------- per-layer: h0 = LN(x) @ conv_w[l] + conv_b[l] ----------------
__global__ void h0_kernel(const float* __restrict__ lng, const float* __restrict__ lnb,
                          const float* __restrict__ W,   const float* __restrict__ cb,
                          int l)
{
    __shared__ float sW[HID * HID];
    __shared__ float sg[HID], sb2[HID], scb[HID];
    int t = threadIdx.x;
    if (t < HID * HID) sW[t] = W[l * HID * HID + t];
    if (t < HID) { sg[t] = lng[l * HID + t]; sb2[t] = lnb[l * HID + t]; scb[t] = cb[l * HID + t]; }
    __syncthreads();

    int r = blockIdx.x * blockDim.x + threadIdx.x;
    if (r >= NN * DH) return;

    float v[HID];
    #pragma unroll
    for (int h = 0; h < HID; h++) v[h] = g_xproj[(size_t)r * HID + h];
    float mean = 0.f;
    #pragma unroll
    for (int h = 0; h < HID; h++) mean += v[h];
    mean *= (1.0f / HID);
    float var = 0.f;
    #pragma unroll
    for (int h = 0; h < HID; h++) { float d = v[h] - mean; var += d * d; }
    var *= (1.0f / HID);
    float rs = rsqrtf(var + 1e-5f);
    float y[HID];
    #pragma unroll
    for (int h = 0; h < HID; h++) y[h] = (v[h] - mean) * rs * sg[h] + sb2[h];

    #pragma unroll
    for (int c = 0; c < HID; c++) {
        float acc = scb[c];
        #pragma unroll
        for (int h = 0; h < HID; h++) acc += y[h] * sW[h * HID + c];
        g_h0[(size_t)r * ROW12 + c] = acc;
    }
}

// ---------------- scatter node->edge:  m[e*d+j] += alpha(k,j) * h0[n*d+j] ----------------
__global__ void scatter_edge_kernel(const int* __restrict__ ni, const int* __restrict__ ei)
{
    int k = blockIdx.x * blockDim.x + threadIdx.x;
    if (k >= NNZV) return;
    int n = ni[k], e = ei[k];
    const float* src = g_h0 + (size_t)n * DH * ROW12;
    float*       dst = g_m  + (size_t)e * DH * ROW12;
    const float* hs  = g_hsheaf + (size_t)k * DH;
    #pragma unroll
    for (int j = 0; j < DH; j++) {
        float al = hs[j];
        const float4 s0 = *(const float4*)(src + j * ROW12);
        const float4 s1 = *(const float4*)(src + j * ROW12 + 4);
        float s2 = src[j * ROW12 + 8];
        atomicAdd((float4*)(dst + j * ROW12),
                  make_float4(al * s0.x, al * s0.y, al * s0.z, al * s0.w));
        atomicAdd((float4*)(dst + j * ROW12 + 4),
                  make_float4(al * s1.x, al * s1.y, al * s1.z, al * s1.w));
        atomicAdd(dst + j * ROW12 + 8, al * s2);
    }
}

// ---------------- scatter edge->node: acc[n*d+j] += alpha(k,j) * Be(e) * m[e*d+j] ----------------
__global__ void scatter_node_kernel(const int* __restrict__ ni, const int* __restrict__ ei)
{
    int k = blockIdx.x * blockDim.x + threadIdx.x;
    if (k >= NNZV) return;
    int n = ni[k], e = ei[k];
    int ce = g_cnt_edge[e];
    float be = (ce > 0) ? (1.0f / (float)ce) : 0.f;
    const float* src = g_m   + (size_t)e * DH * ROW12;
    float*       dst = g_acc + (size_t)n * DH * ROW12;
    const float* hs  = g_hsheaf + (size_t)k * DH;
    #pragma unroll
    for (int j = 0; j < DH; j++) {
        float al = hs[j] * be;
        const float4 s0 = *(const float4*)(src + j * ROW12);
        const float4 s1 = *(const float4*)(src + j * ROW12 + 4);
        float s2 = src[j * ROW12 + 8];
        atomicAdd((float4*)(dst + j * ROW12),
                  make_float4(al * s0.x, al * s0.y, al * s0.z, al * s0.w));
        atomicAdd((float4*)(dst + j * ROW12 + 4),
                  make_float4(al * s1.x, al * s1.y, al * s1.z, al * s1.w));
        atomicAdd(dst + j * ROW12 + 8, al * s2);
    }
}

// ---------------- finalize: x = [elu](acc*Dv + h0 + conv_bias[l]) ----------------
__global__ void finalize_kernel(const float* __restrict__ cbias, int l)
{
    __shared__ float sb[HID];
    if (threadIdx.x < HID) sb[threadIdx.x] = cbias[l * HID + threadIdx.x];
    __syncthreads();

    int r = blockIdx.x * blockDim.x + threadIdx.x;
    if (r >= NN * DH) return;
    int n = r / DH;
    int cn = g_cnt_node[n];
    float dv = (cn > 0) ? (1.0f / (float)cn) : 0.f;
    #pragma unroll
    for (int h = 0; h < HID; h++) {
        float v = g_acc[(size_t)r * ROW12 + h] * dv
                + g_h0[(size_t)r * ROW12 + h] + sb[h];
        if (l == 0) v = (v > 0.f) ? v : expm1f(v);   // ELU on all but last layer
        g_xproj[(size_t)r * HID + h] = v;
    }
}

// ---------------- final GEMM: C[20000,4968] = Xf[20000,54] @ W2[54,4968] + b2 ----------------
// 128x128 tile, 8x8 microtile, K split into 2 chunks of 27 (static smem < 48KB)
#define GBM 128
#define GBN 128
#define GBK 27
#define AST 132   // padded A smem stride (float4-aligned, reduced bank conflict)

__global__ void __launch_bounds__(256, 2)
lin2_gemm_kernel(const float* __restrict__ Bw, const float* __restrict__ bias,
                 float* __restrict__ C)
{
    __shared__ float As[GBK * AST];   // A^T tile: As[k][m]
    __shared__ float Bs[GBK * GBN];   // Bs[k][n]

    int n0 = blockIdx.x * GBN;
    int m0 = blockIdx.y * GBM;
    int tid = threadIdx.x;
    int tx = tid & 15, ty = tid >> 4;

    float acc[8][8];
    #pragma unroll
    for (int i = 0; i < 8; i++)
        #pragma unroll
        for (int j = 0; j < 8; j++) acc[i][j] = 0.f;

    for (int kk = 0; kk < PROJ; kk += GBK) {
        for (int i = tid; i < GBM * GBK; i += 256) {
            int m = i / GBK, k = i - m * GBK;
            int gm = m0 + m;
            As[k * AST + m] = (gm < NN) ? g_xproj[(size_t)gm * PROJ + kk + k] : 0.f;
        }
        for (int i = tid; i < GBK * GBN; i += 256) {
            int k = i >> 7, n = i & 127;
            int gn = n0 + n;
            Bs[i] = (gn < OUTD) ? Bw[(size_t)(kk + k) * OUTD + gn] : 0.f;
        }
        __syncthreads();

        #pragma unroll 9
        for (int k = 0; k < GBK; k++) {
            float a[8], b[8];
            *(float4*)&a[0] = *(const float4*)&As[k * AST + ty * 8];
            *(float4*)&a[4] = *(const float4*)&As[k * AST + ty * 8 + 4];
            *(float4*)&b[0] = *(const float4*)&Bs[k * GBN + tx * 8];
            *(float4*)&b[4] = *(const float4*)&Bs[k * GBN + tx * 8 + 4];
            #pragma unroll
            for (int i = 0; i < 8; i++)
                #pragma unroll
                for (int j = 0; j < 8; j++)
                    acc[i][j] += a[i] * b[j];
        }
        __syncthreads();
    }

    // epilogue: add bias, store (4968 % 8 == 0 -> threads are fully in or out in N)
    int nb = n0 + tx * 8;
    if (nb < OUTD) {
        float bv[8];
        #pragma unroll
        for (int j = 0; j < 8; j++) bv[j] = bias[nb + j];
        #pragma unroll
        for (int i = 0; i < 8; i++) {
            int gm = m0 + ty * 8 + i;
            if (gm >= NN) continue;
            float* crow = C + (size_t)gm * OUTD + nb;
            float4 v0 = make_float4(acc[i][0] + bv[0], acc[i][1] + bv[1],
                                    acc[i][2] + bv[2], acc[i][3] + bv[3]);
            float4 v1 = make_float4(acc[i][4] + bv[4], acc[i][5] + bv[5],
                                    acc[i][6] + bv[6], acc[i][7] + bv[7]);
            *(float4*)crow       = v0;
            *(float4*)(crow + 4) = v1;
        }
    }
}

// ---------------- launch ----------------
extern "C" void kernel_launch(void* const* d_in, const int* in_sizes, int n_in,
                              void* d_out, int out_size)
{
    const float* x        = (const float*)d_in[0];
    const float* hedge    = (const float*)d_in[1];
    const int*   node_idx = (const int*)  d_in[2];
    const int*   edge_idx = (const int*)  d_in[3];
    const float* lin_w    = (const float*)d_in[4];
    const float* lin_b    = (const float*)d_in[5];
    const float* s_ln_g   = (const float*)d_in[6];
    const float* s_ln_b   = (const float*)d_in[7];
    const float* sheaf_w  = (const float*)d_in[8];
    const float* sheaf_b  = (const float*)d_in[9];
    const float* c_ln_g   = (const float*)d_in[10];
    const float* c_ln_b   = (const float*)d_in[11];
    const float* conv_w   = (const float*)d_in[12];
    const float* conv_b   = (const float*)d_in[13];
    const float* conv_bias= (const float*)d_in[14];
    const float* lin2_w   = (const float*)d_in[15];
    const float* lin2_b   = (const float*)d_in[16];
    float* out = (float*)d_out;

    // counts
    zero_counts_kernel<<<(NN + 255) / 256, 256>>>();
    // input projection + means
    proj_kernel<<<(NN + EE) / 8, 64>>>(x, hedge, lin_w, lin_b);
    // sheaf coefficients + degrees
    sheaf_kernel<<<(NNZV + 255) / 256, 256>>>(node_idx, edge_idx,
                                              s_ln_g, s_ln_b, sheaf_w, sheaf_b);

    for (int l = 0; l < NLAY; l++) {
        zero_layer_kernel<<<(NN * DH * ROW12 + 255) / 256, 256>>>();
        h0_kernel<<<(NN * DH + 255) / 256, 256>>>(c_ln_g, c_ln_b, conv_w, conv_b, l);
        scatter_edge_kernel<<<(NNZV + 255) / 256, 256>>>(node_idx, edge_idx);
        scatter_node_kernel<<<(NNZV + 255) / 256, 256>>>(node_idx, edge_idx);
        finalize_kernel<<<(NN * DH + 255) / 256, 256>>>(conv_bias, l);
    }

    dim3 grid((OUTD + GBN - 1) / GBN, (NN + GBM - 1) / GBM);  // 39 x 157
    lin2_gemm_kernel<<<grid, 256>>>(lin2_w, lin2_b, out);
}